// round 5
// baseline (speedup 1.0000x reference)
#include <cuda_runtime.h>
#include <math_constants.h>

#define BSZ      1024
#define KCOLS    66560              // BSZ + 65536
#define KV4      (KCOLS / 4)        // 16640 float4 per row = 65 per thread
#define NTHREADS 256
#define NWARPS   (NTHREADS / 32)
#define CAP      4096               // candidate slots (expected ~410 used)
#define TCAND    2.5f

__device__ float    g_row_loss[BSZ];
__device__ unsigned g_done = 0;     // reset by last block each launch -> replay-safe

__global__ __launch_bounds__(NTHREADS) void wl_row_kernel(const float* __restrict__ logits,
                                                          float* __restrict__ out)
{
    const int row = blockIdx.x;
    const float4* __restrict__ rp =
        reinterpret_cast<const float4*>(logits + (size_t)row * KCOLS);

    __shared__ float s_cand[CAP];
    __shared__ int   s_cnt;
    __shared__ float s_sum[NWARPS];
    __shared__ float s_max[NWARPS];
    __shared__ float s_par[4];          // inv, m, dl, fast-flag
    __shared__ int   s_last;

    const int tid = threadIdx.x;
    if (tid == 0) s_cnt = 0;
    __syncthreads();

    // ---- Pass 1: lean streaming body; capture behind warp-uniform rare branch --
    float s0 = 0.f, s1 = 0.f, s2 = 0.f, s3 = 0.f;
    float mxo = -CUDART_INF_F;          // off-diag candidate max (exact off-diag
                                        // max whenever any off-diag elem >= TCAND)
    #pragma unroll 5
    for (int v = tid; v < KV4; v += NTHREADS) {
        float4 x = rp[v];
        s0 += __expf(x.x);
        s1 += __expf(x.y);
        s2 += __expf(x.z);
        s3 += __expf(x.w);
        float mx4 = fmaxf(fmaxf(x.x, x.y), fmaxf(x.z, x.w));
        // warp-uniform entry: no divergence on the common (not-taken) path
        if (__any_sync(0xffffffffu, mx4 >= TCAND)) {
            if (mx4 >= TCAND) {         // ~2.4% of lanes
                const int base = v * 4;
                if (x.x >= TCAND && base + 0 != row) { mxo = fmaxf(mxo, x.x); int p = atomicAdd(&s_cnt, 1); if (p < CAP) s_cand[p] = x.x; }
                if (x.y >= TCAND && base + 1 != row) { mxo = fmaxf(mxo, x.y); int p = atomicAdd(&s_cnt, 1); if (p < CAP) s_cand[p] = x.y; }
                if (x.z >= TCAND && base + 2 != row) { mxo = fmaxf(mxo, x.z); int p = atomicAdd(&s_cnt, 1); if (p < CAP) s_cand[p] = x.z; }
                if (x.w >= TCAND && base + 3 != row) { mxo = fmaxf(mxo, x.w); int p = atomicAdd(&s_cnt, 1); if (p < CAP) s_cand[p] = x.w; }
            }
        }
    }

    float sum = (s0 + s1) + (s2 + s3);
    #pragma unroll
    for (int o = 16; o; o >>= 1) {
        sum += __shfl_xor_sync(0xffffffffu, sum, o);
        mxo  = fmaxf(mxo, __shfl_xor_sync(0xffffffffu, mxo, o));
    }
    if ((tid & 31) == 0) { s_sum[tid >> 5] = sum; s_max[tid >> 5] = mxo; }
    __syncthreads();

    if (tid == 0) {
        float S = 0.f, M = -CUDART_INF_F;
        #pragma unroll
        for (int i = 0; i < NWARPS; i++) { S += s_sum[i]; M = fmaxf(M, s_max[i]); }
        float dl       = logits[(size_t)row * KCOLS + row];     // cache hit
        float neg_mean = (S - __expf(dl)) * (1.0f / (float)(KCOLS - 1));
        float inv      = 1.0f / neg_mean;
        // g(l)=l*exp(l)*inv monotone for l >= -1; M >= TCAND > 0 on fast path, so
        // g(M) is the EXACT off-diagonal max of u. Row max m = max(g(M), dl).
        float gmo = M * __expf(M) * inv;
        float m   = fmaxf(gmo, dl);
        float gT  = TCAND * __expf(TCAND) * inv;  // bound on any non-candidate u
        bool fast = (M >= TCAND) && (neg_mean > 0.f) &&
                    (gT <= m - 30.f) && (s_cnt <= CAP);
        s_par[0] = inv; s_par[1] = m; s_par[2] = dl; s_par[3] = fast ? 1.f : 0.f;
    }
    __syncthreads();

    const float inv = s_par[0], m = s_par[1], dl = s_par[2];
    const bool  fast = (s_par[3] != 0.f);

    if (fast) {
        // ---- Pass 2 (fast): captured candidates only — zero memory re-read -----
        const int nc = s_cnt;
        float sl = 0.f;
        for (int i = tid; i < nc; i += NTHREADS) {
            float l = s_cand[i];
            sl += __expf(l * __expf(l) * inv - m);
        }
        #pragma unroll
        for (int o = 16; o; o >>= 1) sl += __shfl_xor_sync(0xffffffffu, sl, o);
        if ((tid & 31) == 0) s_sum[tid >> 5] = sl;
        __syncthreads();
        if (tid == 0) {
            float s = __expf(dl - m);           // diagonal term (u_ii = dl)
            #pragma unroll
            for (int i = 0; i < NWARPS; i++) s += s_sum[i];
            g_row_loss[row] = m + logf(s) - dl;
        }
    } else {
        // ---- Pass 2 (robust fallback): full online-LSE re-read ------------------
        float mt = -CUDART_INF_F, st = 0.f;
        for (int v = tid; v < KV4; v += NTHREADS) {
            float4 x = rp[v];
            float c[4] = {x.x, x.y, x.z, x.w};
            #pragma unroll
            for (int q = 0; q < 4; q++) {
                int   j = v * 4 + q;
                float u = (j == row) ? dl : c[q] * __expf(c[q]) * inv;
                float nm = fmaxf(mt, u);
                st = st * __expf(mt - nm) + __expf(u - nm);
                mt = nm;
            }
        }
        #pragma unroll
        for (int o = 16; o; o >>= 1) {
            float om = __shfl_xor_sync(0xffffffffu, mt, o);
            float os = __shfl_xor_sync(0xffffffffu, st, o);
            float nm = fmaxf(mt, om);
            st = st * __expf(mt - nm) + os * __expf(om - nm);
            mt = nm;
        }
        if ((tid & 31) == 0) { s_sum[tid >> 5] = st; s_max[tid >> 5] = mt; }
        __syncthreads();
        if (tid == 0) {
            float m2 = -CUDART_INF_F, s2v = 0.f;
            #pragma unroll
            for (int i = 0; i < NWARPS; i++) m2 = fmaxf(m2, s_max[i]);
            #pragma unroll
            for (int i = 0; i < NWARPS; i++) s2v += s_sum[i] * __expf(s_max[i] - m2);
            g_row_loss[row] = m2 + logf(s2v) - dl;
        }
    }

    // ---- Fused final reduction: last finishing block sums the 1024 row losses --
    if (tid == 0) {
        __threadfence();
        unsigned t = atomicAdd(&g_done, 1u);
        s_last = (t == (unsigned)(gridDim.x - 1));
    }
    __syncthreads();
    if (s_last) {
        float v = 0.f;
        #pragma unroll
        for (int i = tid; i < BSZ; i += NTHREADS) v += __ldcg(&g_row_loss[i]);
        #pragma unroll
        for (int o = 16; o; o >>= 1) v += __shfl_xor_sync(0xffffffffu, v, o);
        if ((tid & 31) == 0) s_sum[tid >> 5] = v;
        __syncthreads();
        if (tid == 0) {
            float t = 0.f;
            #pragma unroll
            for (int i = 0; i < NWARPS; i++) t += s_sum[i];
            out[0] = t * (1.0f / (float)BSZ);
            g_done = 0;                         // reset for next graph replay
        }
    }
}

extern "C" void kernel_launch(void* const* d_in, const int* in_sizes, int n_in,
                              void* d_out, int out_size)
{
    const float* logits = (const float*)d_in[0];
    (void)in_sizes; (void)n_in; (void)out_size;
    wl_row_kernel<<<BSZ, NTHREADS>>>(logits, (float*)d_out);
}

// round 6
// speedup vs baseline: 1.0365x; 1.0365x over previous
#include <cuda_runtime.h>
#include <math_constants.h>

#define BSZ      1024
#define KCOLS    66560              // BSZ + 65536
#define KV4      (KCOLS / 4)        // 16640 float4 per row = 65 per thread
#define NTHREADS 256
#define NWARPS   (NTHREADS / 32)
#define VCAP     1408               // captured-vector slots (expect ~250-400 used)
#define TCAND    2.5f

__device__ float    g_row_loss[BSZ];
__device__ unsigned g_done = 0;     // reset by last block each launch -> replay-safe

__global__ __launch_bounds__(NTHREADS) void wl_row_kernel(const float* __restrict__ logits,
                                                          float* __restrict__ out)
{
    const int row = blockIdx.x;
    const float4* __restrict__ rp =
        reinterpret_cast<const float4*>(logits + (size_t)row * KCOLS);

    __shared__ __align__(16) float4 s_vc[VCAP];   // captured vectors (22.5 KB)
    __shared__ int   s_vi[VCAP];                  // their float4 indices (5.6 KB)
    __shared__ int   s_cnt;
    __shared__ float s_sum[NWARPS];
    __shared__ float s_max[NWARPS];
    __shared__ float s_par[4];                    // inv, m, dl, fast-flag
    __shared__ int   s_last;

    const int tid = threadIdx.x;
    if (tid == 0) s_cnt = 0;
    __syncthreads();

    // ---- Pass 1: minimal streaming body. Per-VECTOR capture, no per-element work
    float a0 = 0.f, a1 = 0.f, a2 = 0.f, a3 = 0.f;
    #pragma unroll 5
    for (int v = tid; v < KV4; v += NTHREADS) {
        float4 x = rp[v];
        a0 += __expf(x.x);
        a1 += __expf(x.y);
        a2 += __expf(x.z);
        a3 += __expf(x.w);
        float mx4 = fmaxf(fmaxf(x.x, x.y), fmaxf(x.z, x.w));
        if (mx4 >= TCAND) {             // ~2.4% of lanes: push whole vector
            int p = atomicAdd(&s_cnt, 1);
            if (p < VCAP) { s_vc[p] = x; s_vi[p] = v; }
        }
    }

    float sum = (a0 + a1) + (a2 + a3);
    #pragma unroll
    for (int o = 16; o; o >>= 1) sum += __shfl_xor_sync(0xffffffffu, sum, o);
    if ((tid & 31) == 0) s_sum[tid >> 5] = sum;
    __syncthreads();

    // ---- Filter stage (smem-only): off-diag max M over true candidates --------
    const int ncv = min(s_cnt, VCAP);
    float mxo = -CUDART_INF_F;
    for (int i = tid; i < ncv; i += NTHREADS) {
        float4 x = s_vc[i];
        const int base = s_vi[i] * 4;
        if (x.x >= TCAND && base + 0 != row) mxo = fmaxf(mxo, x.x);
        if (x.y >= TCAND && base + 1 != row) mxo = fmaxf(mxo, x.y);
        if (x.z >= TCAND && base + 2 != row) mxo = fmaxf(mxo, x.z);
        if (x.w >= TCAND && base + 3 != row) mxo = fmaxf(mxo, x.w);
    }
    #pragma unroll
    for (int o = 16; o; o >>= 1) mxo = fmaxf(mxo, __shfl_xor_sync(0xffffffffu, mxo, o));
    if ((tid & 31) == 0) s_max[tid >> 5] = mxo;
    __syncthreads();

    if (tid == 0) {
        float S = 0.f, M = -CUDART_INF_F;
        #pragma unroll
        for (int i = 0; i < NWARPS; i++) { S += s_sum[i]; M = fmaxf(M, s_max[i]); }
        float dl       = logits[(size_t)row * KCOLS + row];     // cache hit
        float neg_mean = (S - __expf(dl)) * (1.0f / (float)(KCOLS - 1));
        float inv      = 1.0f / neg_mean;
        // g(l)=l*exp(l)*inv monotone for l >= -1; M >= TCAND > 0 on fast path, so
        // g(M) is the EXACT off-diagonal max of u. Row max m = max(g(M), dl).
        float gmo = M * __expf(M) * inv;
        float m   = fmaxf(gmo, dl);
        float gT  = TCAND * __expf(TCAND) * inv;  // bound on any non-candidate u
        bool fast = (M >= TCAND) && (neg_mean > 0.f) &&
                    (gT <= m - 30.f) && (s_cnt <= VCAP);
        s_par[0] = inv; s_par[1] = m; s_par[2] = dl; s_par[3] = fast ? 1.f : 0.f;
    }
    __syncthreads();

    const float inv = s_par[0], m = s_par[1], dl = s_par[2];
    const bool  fast = (s_par[3] != 0.f);

    if (fast) {
        // ---- Pass 2 (fast): filtered candidates from smem — zero re-read -------
        float sl = 0.f;
        for (int i = tid; i < ncv; i += NTHREADS) {
            float4 x = s_vc[i];
            const int base = s_vi[i] * 4;
            if (x.x >= TCAND && base + 0 != row) sl += __expf(x.x * __expf(x.x) * inv - m);
            if (x.y >= TCAND && base + 1 != row) sl += __expf(x.y * __expf(x.y) * inv - m);
            if (x.z >= TCAND && base + 2 != row) sl += __expf(x.z * __expf(x.z) * inv - m);
            if (x.w >= TCAND && base + 3 != row) sl += __expf(x.w * __expf(x.w) * inv - m);
        }
        #pragma unroll
        for (int o = 16; o; o >>= 1) sl += __shfl_xor_sync(0xffffffffu, sl, o);
        if ((tid & 31) == 0) s_sum[tid >> 5] = sl;
        __syncthreads();
        if (tid == 0) {
            float s = __expf(dl - m);             // diagonal term (u_ii = dl)
            #pragma unroll
            for (int i = 0; i < NWARPS; i++) s += s_sum[i];
            g_row_loss[row] = m + logf(s) - dl;
        }
    } else {
        // ---- Pass 2 (robust fallback): full online-LSE re-read ------------------
        float mt = -CUDART_INF_F, st = 0.f;
        for (int v = tid; v < KV4; v += NTHREADS) {
            float4 x = rp[v];
            float c[4] = {x.x, x.y, x.z, x.w};
            #pragma unroll
            for (int q = 0; q < 4; q++) {
                int   j = v * 4 + q;
                float u = (j == row) ? dl : c[q] * __expf(c[q]) * inv;
                float nm = fmaxf(mt, u);
                st = st * __expf(mt - nm) + __expf(u - nm);
                mt = nm;
            }
        }
        #pragma unroll
        for (int o = 16; o; o >>= 1) {
            float om = __shfl_xor_sync(0xffffffffu, mt, o);
            float os = __shfl_xor_sync(0xffffffffu, st, o);
            float nm = fmaxf(mt, om);
            st = st * __expf(mt - nm) + os * __expf(om - nm);
            mt = nm;
        }
        if ((tid & 31) == 0) { s_sum[tid >> 5] = st; s_max[tid >> 5] = mt; }
        __syncthreads();
        if (tid == 0) {
            float m2 = -CUDART_INF_F, s2v = 0.f;
            #pragma unroll
            for (int i = 0; i < NWARPS; i++) m2 = fmaxf(m2, s_max[i]);
            #pragma unroll
            for (int i = 0; i < NWARPS; i++) s2v += s_sum[i] * __expf(s_max[i] - m2);
            g_row_loss[row] = m2 + logf(s2v) - dl;
        }
    }

    // ---- Fused final reduction: last finishing block sums the 1024 row losses --
    if (tid == 0) {
        __threadfence();
        unsigned t = atomicAdd(&g_done, 1u);
        s_last = (t == (unsigned)(gridDim.x - 1));
    }
    __syncthreads();
    if (s_last) {
        float v = 0.f;
        #pragma unroll
        for (int i = tid; i < BSZ; i += NTHREADS) v += __ldcg(&g_row_loss[i]);
        #pragma unroll
        for (int o = 16; o; o >>= 1) v += __shfl_xor_sync(0xffffffffu, v, o);
        if ((tid & 31) == 0) s_sum[tid >> 5] = v;
        __syncthreads();
        if (tid == 0) {
            float t = 0.f;
            #pragma unroll
            for (int i = 0; i < NWARPS; i++) t += s_sum[i];
            out[0] = t * (1.0f / (float)BSZ);
            g_done = 0;                           // reset for next graph replay
        }
    }
}

extern "C" void kernel_launch(void* const* d_in, const int* in_sizes, int n_in,
                              void* d_out, int out_size)
{
    const float* logits = (const float*)d_in[0];
    (void)in_sizes; (void)n_in; (void)out_size;
    wl_row_kernel<<<BSZ, NTHREADS>>>(logits, (float*)d_out);
}

// round 7
// speedup vs baseline: 1.0485x; 1.0115x over previous
#include <cuda_runtime.h>
#include <math_constants.h>

#define BSZ      1024
#define KCOLS    66560              // BSZ + 65536
#define KV4      (KCOLS / 4)        // 16640 float4 per row = 65 per thread
#define NTHREADS 256
#define NWARPS   (NTHREADS / 32)
#define NBATCH   8                  // 8 batches of 8 float4 + 1 remainder
#define VCAP     1408               // captured-vector slots (expect ~250-400 used)
#define TCAND    2.5f

__device__ float    g_row_loss[BSZ];
__device__ unsigned g_done = 0;     // reset by last block each launch -> replay-safe

__global__ __launch_bounds__(NTHREADS, 5) void wl_row_kernel(const float* __restrict__ logits,
                                                             float* __restrict__ out)
{
    const int row = blockIdx.x;
    const float4* __restrict__ rp =
        reinterpret_cast<const float4*>(logits + (size_t)row * KCOLS);

    __shared__ __align__(16) float4 s_vc[VCAP];   // captured vectors (22.5 KB)
    __shared__ int   s_vi[VCAP];                  // their float4 indices (5.6 KB)
    __shared__ int   s_cnt;
    __shared__ float s_sum[NWARPS];
    __shared__ float s_max[NWARPS];
    __shared__ float s_par[4];                    // inv, m, dl, fast-flag
    __shared__ int   s_last;

    const int tid = threadIdx.x;
    if (tid == 0) s_cnt = 0;
    __syncthreads();

    // ---- Pass 1: 8 back-to-back LDG.128 per batch (MLP=8), then lean compute ---
    float a0 = 0.f, a1 = 0.f, a2 = 0.f, a3 = 0.f;

    #pragma unroll 1
    for (int b = 0; b < NBATCH; b++) {
        const int vb = tid + b * (8 * NTHREADS);
        float4 x0 = rp[vb];
        float4 x1 = rp[vb + 1 * NTHREADS];
        float4 x2 = rp[vb + 2 * NTHREADS];
        float4 x3 = rp[vb + 3 * NTHREADS];
        float4 x4 = rp[vb + 4 * NTHREADS];
        float4 x5 = rp[vb + 5 * NTHREADS];
        float4 x6 = rp[vb + 6 * NTHREADS];
        float4 x7 = rp[vb + 7 * NTHREADS];

        #define WL_DO(X, VIDX)                                                      \
        {                                                                           \
            a0 += __expf((X).x); a1 += __expf((X).y);                               \
            a2 += __expf((X).z); a3 += __expf((X).w);                               \
            float mx4 = fmaxf(fmaxf((X).x, (X).y), fmaxf((X).z, (X).w));            \
            if (mx4 >= TCAND) {                                                     \
                int p = atomicAdd(&s_cnt, 1);                                       \
                if (p < VCAP) { s_vc[p] = (X); s_vi[p] = (VIDX); }                  \
            }                                                                       \
        }

        WL_DO(x0, vb)
        WL_DO(x1, vb + 1 * NTHREADS)
        WL_DO(x2, vb + 2 * NTHREADS)
        WL_DO(x3, vb + 3 * NTHREADS)
        WL_DO(x4, vb + 4 * NTHREADS)
        WL_DO(x5, vb + 5 * NTHREADS)
        WL_DO(x6, vb + 6 * NTHREADS)
        WL_DO(x7, vb + 7 * NTHREADS)
    }
    {   // remainder: 65th float4 per thread
        const int v = tid + NBATCH * (8 * NTHREADS);    // tid + 16384 < 16640
        float4 x = rp[v];
        WL_DO(x, v)
    }
    #undef WL_DO

    float sum = (a0 + a1) + (a2 + a3);
    #pragma unroll
    for (int o = 16; o; o >>= 1) sum += __shfl_xor_sync(0xffffffffu, sum, o);
    if ((tid & 31) == 0) s_sum[tid >> 5] = sum;
    __syncthreads();

    // ---- Filter stage (smem-only): off-diag max M over true candidates ---------
    const int ncv = min(s_cnt, VCAP);
    float mxo = -CUDART_INF_F;
    for (int i = tid; i < ncv; i += NTHREADS) {
        float4 x = s_vc[i];
        const int base = s_vi[i] * 4;
        if (x.x >= TCAND && base + 0 != row) mxo = fmaxf(mxo, x.x);
        if (x.y >= TCAND && base + 1 != row) mxo = fmaxf(mxo, x.y);
        if (x.z >= TCAND && base + 2 != row) mxo = fmaxf(mxo, x.z);
        if (x.w >= TCAND && base + 3 != row) mxo = fmaxf(mxo, x.w);
    }
    #pragma unroll
    for (int o = 16; o; o >>= 1) mxo = fmaxf(mxo, __shfl_xor_sync(0xffffffffu, mxo, o));
    if ((tid & 31) == 0) s_max[tid >> 5] = mxo;
    __syncthreads();

    if (tid == 0) {
        float S = 0.f, M = -CUDART_INF_F;
        #pragma unroll
        for (int i = 0; i < NWARPS; i++) { S += s_sum[i]; M = fmaxf(M, s_max[i]); }
        float dl       = logits[(size_t)row * KCOLS + row];     // cache hit
        float neg_mean = (S - __expf(dl)) * (1.0f / (float)(KCOLS - 1));
        float inv      = 1.0f / neg_mean;
        // g(l)=l*exp(l)*inv monotone for l >= -1; M >= TCAND > 0 on fast path, so
        // g(M) is the EXACT off-diagonal max of u. Row max m = max(g(M), dl).
        float gmo = M * __expf(M) * inv;
        float m   = fmaxf(gmo, dl);
        float gT  = TCAND * __expf(TCAND) * inv;  // bound on any non-candidate u
        bool fast = (M >= TCAND) && (neg_mean > 0.f) &&
                    (gT <= m - 30.f) && (s_cnt <= VCAP);
        s_par[0] = inv; s_par[1] = m; s_par[2] = dl; s_par[3] = fast ? 1.f : 0.f;
    }
    __syncthreads();

    const float inv = s_par[0], m = s_par[1], dl = s_par[2];
    const bool  fast = (s_par[3] != 0.f);

    if (fast) {
        // ---- Pass 2 (fast): filtered candidates from smem — zero re-read -------
        float sl = 0.f;
        for (int i = tid; i < ncv; i += NTHREADS) {
            float4 x = s_vc[i];
            const int base = s_vi[i] * 4;
            if (x.x >= TCAND && base + 0 != row) sl += __expf(x.x * __expf(x.x) * inv - m);
            if (x.y >= TCAND && base + 1 != row) sl += __expf(x.y * __expf(x.y) * inv - m);
            if (x.z >= TCAND && base + 2 != row) sl += __expf(x.z * __expf(x.z) * inv - m);
            if (x.w >= TCAND && base + 3 != row) sl += __expf(x.w * __expf(x.w) * inv - m);
        }
        #pragma unroll
        for (int o = 16; o; o >>= 1) sl += __shfl_xor_sync(0xffffffffu, sl, o);
        if ((tid & 31) == 0) s_sum[tid >> 5] = sl;
        __syncthreads();
        if (tid == 0) {
            float s = __expf(dl - m);             // diagonal term (u_ii = dl)
            #pragma unroll
            for (int i = 0; i < NWARPS; i++) s += s_sum[i];
            g_row_loss[row] = m + logf(s) - dl;
        }
    } else {
        // ---- Pass 2 (robust fallback): full online-LSE re-read ------------------
        float mt = -CUDART_INF_F, st = 0.f;
        for (int v = tid; v < KV4; v += NTHREADS) {
            float4 x = rp[v];
            float c[4] = {x.x, x.y, x.z, x.w};
            #pragma unroll
            for (int q = 0; q < 4; q++) {
                int   j = v * 4 + q;
                float u = (j == row) ? dl : c[q] * __expf(c[q]) * inv;
                float nm = fmaxf(mt, u);
                st = st * __expf(mt - nm) + __expf(u - nm);
                mt = nm;
            }
        }
        #pragma unroll
        for (int o = 16; o; o >>= 1) {
            float om = __shfl_xor_sync(0xffffffffu, mt, o);
            float os = __shfl_xor_sync(0xffffffffu, st, o);
            float nm = fmaxf(mt, om);
            st = st * __expf(mt - nm) + os * __expf(om - nm);
            mt = nm;
        }
        if ((tid & 31) == 0) { s_sum[tid >> 5] = st; s_max[tid >> 5] = mt; }
        __syncthreads();
        if (tid == 0) {
            float m2 = -CUDART_INF_F, s2v = 0.f;
            #pragma unroll
            for (int i = 0; i < NWARPS; i++) m2 = fmaxf(m2, s_max[i]);
            #pragma unroll
            for (int i = 0; i < NWARPS; i++) s2v += s_sum[i] * __expf(s_max[i] - m2);
            g_row_loss[row] = m2 + logf(s2v) - dl;
        }
    }

    // ---- Fused final reduction: last finishing block sums the 1024 row losses --
    if (tid == 0) {
        __threadfence();
        unsigned t = atomicAdd(&g_done, 1u);
        s_last = (t == (unsigned)(gridDim.x - 1));
    }
    __syncthreads();
    if (s_last) {
        float v = 0.f;
        #pragma unroll
        for (int i = tid; i < BSZ; i += NTHREADS) v += __ldcg(&g_row_loss[i]);
        #pragma unroll
        for (int o = 16; o; o >>= 1) v += __shfl_xor_sync(0xffffffffu, v, o);
        if ((tid & 31) == 0) s_sum[tid >> 5] = v;
        __syncthreads();
        if (tid == 0) {
            float t = 0.f;
            #pragma unroll
            for (int i = 0; i < NWARPS; i++) t += s_sum[i];
            out[0] = t * (1.0f / (float)BSZ);
            g_done = 0;                           // reset for next graph replay
        }
    }
}

extern "C" void kernel_launch(void* const* d_in, const int* in_sizes, int n_in,
                              void* d_out, int out_size)
{
    const float* logits = (const float*)d_in[0];
    (void)in_sizes; (void)n_in; (void)out_size;
    wl_row_kernel<<<BSZ, NTHREADS>>>(logits, (float*)d_out);
}